// round 15
// baseline (speedup 1.0000x reference)
#include <cuda_runtime.h>
#include <cuda_bf16.h>
#include <cuda_fp16.h>
#include <cstdint>

#define N_NODES 100000
#define N_EDGES 1600000
#define E_HALF (N_EDGES / 2)
#define IN_CH 128
#define HEADS 4
#define OUT_CH 32
#define HO 128
#define NEG_SLOPE 0.2f
#define EPS 1e-10f

#define SCAN_B 512
#define SCAN_NB ((N_NODES + SCAN_B - 1) / SCAN_B)   // 196

// ---------------- scratch ----------------
__device__ __align__(16) __half g_h16[(size_t)N_NODES * HO];   // 25.6 MB
__device__ __align__(16) float g_ssrc[(size_t)N_NODES * HEADS];
__device__ __align__(16) float g_stgt[(size_t)N_NODES * HEADS];
__device__ __align__(16) __half g_wt16[IN_CH * HO];            // W^T fp16 [n][k]
__device__ int g_deg2[2][N_NODES];
__device__ int g_off2[2][N_NODES];
__device__ int g_cursor2[2][N_NODES];
__device__ int g_bsum2[2][SCAN_NB];
__device__ int g_esrc2[2][E_HALF];
__device__ int g_etgt2[2][E_HALF];
__device__ int g_idx64;

__device__ __forceinline__ int load_idx(const void* eidx, int i) {
    if (g_idx64) return (int)((const long long*)eidx)[i];
    return ((const int*)eidx)[i];
}

// ---------------- zero both degree arrays + dtype detection ----------------
__global__ void zero_detect_kernel(const unsigned int* __restrict__ e) {
    int i = blockIdx.x * blockDim.x + threadIdx.x;
    if (i < N_NODES) {
        g_deg2[0][i] = 0;
        g_deg2[1][i] = 0;
    }
    if (blockIdx.x == 0) {
        __shared__ int any;
        if (threadIdx.x == 0) any = 0;
        __syncthreads();
        unsigned int v = 0;
        for (int k = threadIdx.x; k < 1024; k += blockDim.x) v |= e[2 * k + 1];
        if (v) any = 1;
        __syncthreads();
        if (threadIdx.x == 0) g_idx64 = (any == 0) ? 1 : 0;
    }
}

// ---------------- histogram for pipeline p ----------------
__global__ __launch_bounds__(256) void hist_kernel(const void* __restrict__ eidx,
                                                   int p) {
    int e = blockIdx.x * blockDim.x + threadIdx.x;
    if (e >= E_HALF) return;
    int ge = p * E_HALF + e;
    int tgt = load_idx(eidx, N_EDGES + ge);
    g_etgt2[p][e] = tgt;
    atomicAdd(&g_deg2[p][tgt], 1);
}

// ---------------- scan1: shuffle-based block scan (pipeline p) ----------------
__global__ __launch_bounds__(SCAN_B) void scan1_kernel(int p) {
    __shared__ int warp_sums[16];
    int t = threadIdx.x;
    int lane = t & 31;
    int w = t >> 5;
    int i = blockIdx.x * SCAN_B + t;
    int v = (i < N_NODES) ? g_deg2[p][i] : 0;
    int inc = v;
#pragma unroll
    for (int off = 1; off < 32; off <<= 1) {
        int n = __shfl_up_sync(0xffffffffu, inc, off);
        if (lane >= off) inc += n;
    }
    if (lane == 31) warp_sums[w] = inc;
    __syncthreads();
    if (w == 0) {
        int s = (lane < 16) ? warp_sums[lane] : 0;
#pragma unroll
        for (int off = 1; off < 16; off <<= 1) {
            int n = __shfl_up_sync(0xffffffffu, s, off);
            if (lane >= off) s += n;
        }
        if (lane < 16) warp_sums[lane] = s;
    }
    __syncthreads();
    int base = (w > 0) ? warp_sums[w - 1] : 0;
    if (i < N_NODES) g_off2[p][i] = base + inc - v;
    if (t == SCAN_B - 1) g_bsum2[p][blockIdx.x] = base + inc;
}

// ---------------- scan3: per-block redundant prefix of block sums ----------------
__global__ __launch_bounds__(SCAN_B) void scan3_kernel(int p) {
    __shared__ int s_red[16];
    __shared__ int s_base;
    int bid = blockIdx.x;
    int t = threadIdx.x;
    int lane = t & 31;
    int w = t >> 5;
    int v = (t < bid) ? g_bsum2[p][t] : 0;
#pragma unroll
    for (int off = 16; off > 0; off >>= 1) v += __shfl_xor_sync(0xffffffffu, v, off);
    if (lane == 0) s_red[w] = v;
    __syncthreads();
    if (t == 0) {
        int s = 0;
#pragma unroll
        for (int k = 0; k < 16; k++) s += s_red[k];
        s_base = s;
    }
    __syncthreads();
    int i = bid * SCAN_B + t;
    if (i < N_NODES) {
        int o = g_off2[p][i] + s_base;
        g_off2[p][i] = o;
        g_cursor2[p][i] = o;
    }
}

// ---------------- scatter (pipeline p) ----------------
__global__ __launch_bounds__(256) void scatter_kernel(const void* __restrict__ eidx,
                                                      int p) {
    int e = blockIdx.x * blockDim.x + threadIdx.x;
    if (e >= E_HALF) return;
    int ge = p * E_HALF + e;
    int src = load_idx(eidx, ge);
    int tgt = g_etgt2[p][e];
    int slot = atomicAdd(&g_cursor2[p][tgt], 1);
    g_esrc2[p][slot] = src;
}

// ---------------- W prep: g_wt16[n][k] = fp16(W[k][n]) ----------------
__global__ __launch_bounds__(256) void wprep_kernel(const float* __restrict__ W) {
    int i = blockIdx.x * blockDim.x + threadIdx.x;
    if (i >= IN_CH * HO) return;
    int n = i & 127;
    int k = i >> 7;
    g_wt16[n * IN_CH + k] = __float2half(W[k * HO + n]);
}

// ---------------- HMMA GEMM + fused scores ----------------
#define A_STRIDE 136
#define W_STRIDE 136
#define ACC_STRIDE 132
#define SMEM_A_BYTES (64 * A_STRIDE * 2)            // 17408
#define SMEM_W_BYTES (128 * W_STRIDE * 2)           // 34816
#define SMEM_TOTAL (SMEM_A_BYTES + SMEM_W_BYTES)    // 52224

extern __shared__ char dsm[];

__global__ __launch_bounds__(128) void gemm_kernel(
    const float* __restrict__ x, const float* __restrict__ att) {
    __shared__ float s_att[HEADS * 2 * OUT_CH];     // 256

    const int tid = threadIdx.x;
    const int warpid = tid >> 5;
    const int lane = tid & 31;
    const int g = lane >> 2;
    const int tg = lane & 3;
    const int row0 = blockIdx.x * 64;

    __half* As = (__half*)dsm;
    __half* Ws = (__half*)(dsm + SMEM_A_BYTES);

    s_att[tid] = att[tid];
    s_att[tid + 128] = att[tid + 128];

    {
        const uint4* wsrc = (const uint4*)g_wt16;
#pragma unroll
        for (int j = 0; j < 16; j++) {
            int i = tid + j * 128;
            int row = i >> 4;
            int c8 = i & 15;
            *(uint4*)&Ws[row * W_STRIDE + c8 * 8] = wsrc[i];
        }
    }

    {
#pragma unroll
        for (int j = 0; j < 16; j++) {
            int i = tid + j * 128;
            int row = i >> 5;
            int c4 = i & 31;
            int grow = row0 + row;
            float4 v = make_float4(0.f, 0.f, 0.f, 0.f);
            if (grow < N_NODES)
                v = ((const float4*)x)[(size_t)grow * (IN_CH / 4) + c4];
            __half2 h0 = __float22half2_rn(make_float2(v.x, v.y));
            __half2 h1 = __float22half2_rn(make_float2(v.z, v.w));
            uint2 p;
            p.x = *(unsigned int*)&h0;
            p.y = *(unsigned int*)&h1;
            *(uint2*)&As[row * A_STRIDE + c4 * 4] = p;
        }
    }
    __syncthreads();

    float acc[16][4];
#pragma unroll
    for (int nt = 0; nt < 16; nt++)
#pragma unroll
        for (int j = 0; j < 4; j++) acc[nt][j] = 0.f;

    const int arow = warpid * 16 + g;
#pragma unroll
    for (int ks = 0; ks < 8; ks++) {
        int kcol = ks * 16 + tg * 2;
        uint32_t a0 = *(uint32_t*)&As[arow * A_STRIDE + kcol];
        uint32_t a1 = *(uint32_t*)&As[(arow + 8) * A_STRIDE + kcol];
        uint32_t a2 = *(uint32_t*)&As[arow * A_STRIDE + kcol + 8];
        uint32_t a3 = *(uint32_t*)&As[(arow + 8) * A_STRIDE + kcol + 8];
#pragma unroll
        for (int nt = 0; nt < 16; nt++) {
            int n = nt * 8 + g;
            uint32_t b0 = *(uint32_t*)&Ws[n * W_STRIDE + kcol];
            uint32_t b1 = *(uint32_t*)&Ws[n * W_STRIDE + kcol + 8];
            asm volatile(
                "mma.sync.aligned.m16n8k16.row.col.f32.f16.f16.f32 "
                "{%0,%1,%2,%3}, {%4,%5,%6,%7}, {%8,%9}, {%0,%1,%2,%3};"
                : "+f"(acc[nt][0]), "+f"(acc[nt][1]),
                  "+f"(acc[nt][2]), "+f"(acc[nt][3])
                : "r"(a0), "r"(a1), "r"(a2), "r"(a3), "r"(b0), "r"(b1));
        }
    }
    __syncthreads();

    float* sAcc = (float*)dsm;
    {
        int r0 = warpid * 16 + g;
#pragma unroll
        for (int nt = 0; nt < 16; nt++) {
            int col = nt * 8 + tg * 2;
            *(float2*)&sAcc[r0 * ACC_STRIDE + col] =
                make_float2(acc[nt][0], acc[nt][1]);
            *(float2*)&sAcc[(r0 + 8) * ACC_STRIDE + col] =
                make_float2(acc[nt][2], acc[nt][3]);
        }
    }
    __syncwarp();

    const int head = lane >> 3;
    const int o0 = (lane & 7) * 4;
    float as0 = s_att[head * 64 + o0], as1 = s_att[head * 64 + o0 + 1],
          as2 = s_att[head * 64 + o0 + 2], as3 = s_att[head * 64 + o0 + 3];
    float at0 = s_att[head * 64 + 32 + o0], at1 = s_att[head * 64 + 32 + o0 + 1],
          at2 = s_att[head * 64 + 32 + o0 + 2], at3 = s_att[head * 64 + 32 + o0 + 3];

#pragma unroll
    for (int rr = 0; rr < 16; rr++) {
        int row = warpid * 16 + rr;
        int grow = row0 + row;
        float4 c = *(float4*)&sAcc[row * ACC_STRIDE + lane * 4];
        if (grow < N_NODES) {
            __half2 t0 = __float22half2_rn(make_float2(c.x, c.y));
            __half2 t1 = __float22half2_rn(make_float2(c.z, c.w));
            uint2 p;
            p.x = *(unsigned int*)&t0;
            p.y = *(unsigned int*)&t1;
            ((uint2*)(g_h16 + (size_t)grow * HO))[lane] = p;
        }
        float ps = c.x * as0 + c.y * as1 + c.z * as2 + c.w * as3;
        float pt = c.x * at0 + c.y * at1 + c.z * at2 + c.w * at3;
#pragma unroll
        for (int off = 4; off > 0; off >>= 1) {
            ps += __shfl_xor_sync(0xffffffffu, ps, off);
            pt += __shfl_xor_sync(0xffffffffu, pt, off);
        }
        if ((lane & 7) == 0 && grow < N_NODES) {
            g_ssrc[grow * HEADS + head] = ps;
            g_stgt[grow * HEADS + head] = pt;
        }
    }
}

// ---------------- gather-reduce: 2 nodes/warp, walks both bucket lists ----------------
__global__ __launch_bounds__(256) void gather_kernel(
    float* __restrict__ out, const float* __restrict__ bias) {
    int warp = (blockIdx.x * blockDim.x + threadIdx.x) >> 5;
    int lane = threadIdx.x & 31;
    int grp = lane >> 4;
    int li = lane & 15;
    int node = warp * 2 + grp;
    if (node >= N_NODES) return;
    int head = li >> 2;

    float st = g_stgt[node * HEADS + head];

    float4 accA = make_float4(0.f, 0.f, 0.f, 0.f);
    float4 accB = make_float4(0.f, 0.f, 0.f, 0.f);
    float den = 0.f;

    const uint4* h16 = (const uint4*)g_h16;

#pragma unroll
    for (int p = 0; p < 2; p++) {
        int start = g_off2[p][node];
        int cnt = g_deg2[p][node];
        const int* esrc = g_esrc2[p];
        int j = 0;
        for (; j + 2 <= cnt; j += 2) {
            int s0 = esrc[start + j];
            int s1 = esrc[start + j + 1];
            float sc0 = g_ssrc[s0 * HEADS + head] + st;
            float sc1 = g_ssrc[s1 * HEADS + head] + st;
            uint4 v0 = h16[(size_t)s0 * 16 + li];
            uint4 v1 = h16[(size_t)s1 * 16 + li];
            float lr0 = sc0 > 0.f ? sc0 : NEG_SLOPE * sc0;
            float lr1 = sc1 > 0.f ? sc1 : NEG_SLOPE * sc1;
            float w0 = __expf(-lr0);
            float w1 = __expf(-lr1);
            float2 p00 = __half22float2(*(const __half2*)&v0.x);
            float2 p01 = __half22float2(*(const __half2*)&v0.y);
            float2 p02 = __half22float2(*(const __half2*)&v0.z);
            float2 p03 = __half22float2(*(const __half2*)&v0.w);
            float2 p10 = __half22float2(*(const __half2*)&v1.x);
            float2 p11 = __half22float2(*(const __half2*)&v1.y);
            float2 p12 = __half22float2(*(const __half2*)&v1.z);
            float2 p13 = __half22float2(*(const __half2*)&v1.w);
            accA.x += w0 * p00.x + w1 * p10.x;
            accA.y += w0 * p00.y + w1 * p10.y;
            accA.z += w0 * p01.x + w1 * p11.x;
            accA.w += w0 * p01.y + w1 * p11.y;
            accB.x += w0 * p02.x + w1 * p12.x;
            accB.y += w0 * p02.y + w1 * p12.y;
            accB.z += w0 * p03.x + w1 * p13.x;
            accB.w += w0 * p03.y + w1 * p13.y;
            den += w0 + w1;
        }
        if (j < cnt) {
            int s0 = esrc[start + j];
            float sc0 = g_ssrc[s0 * HEADS + head] + st;
            uint4 v0 = h16[(size_t)s0 * 16 + li];
            float lr0 = sc0 > 0.f ? sc0 : NEG_SLOPE * sc0;
            float w0 = __expf(-lr0);
            float2 p00 = __half22float2(*(const __half2*)&v0.x);
            float2 p01 = __half22float2(*(const __half2*)&v0.y);
            float2 p02 = __half22float2(*(const __half2*)&v0.z);
            float2 p03 = __half22float2(*(const __half2*)&v0.w);
            accA.x += w0 * p00.x;
            accA.y += w0 * p00.y;
            accA.z += w0 * p01.x;
            accA.w += w0 * p01.y;
            accB.x += w0 * p02.x;
            accB.y += w0 * p02.y;
            accB.z += w0 * p03.x;
            accB.w += w0 * p03.y;
            den += w0;
        }
    }

    float d = den > EPS ? den : EPS;
    float inv = 1.0f / d;
    float4 b0 = ((const float4*)bias)[li * 2];
    float4 b1 = ((const float4*)bias)[li * 2 + 1];
    float4 o0, o1;
    o0.x = accA.x * inv + b0.x;
    o0.y = accA.y * inv + b0.y;
    o0.z = accA.z * inv + b0.z;
    o0.w = accA.w * inv + b0.w;
    o1.x = accB.x * inv + b1.x;
    o1.y = accB.y * inv + b1.y;
    o1.z = accB.z * inv + b1.z;
    o1.w = accB.w * inv + b1.w;
    float4* op = (float4*)(out + (size_t)node * HO) + li * 2;
    op[0] = o0;
    op[1] = o1;
}

extern "C" void kernel_launch(void* const* d_in, const int* in_sizes, int n_in,
                              void* d_out, int out_size) {
    const float* x = (const float*)d_in[0];
    const void* eidx = d_in[1];
    const float* W = (const float*)d_in[2];
    const float* att = (const float*)d_in[3];
    const float* bias = (const float*)d_in[4];
    float* out = (float*)d_out;

    static cudaStream_t s2 = nullptr, s3 = nullptr;
    static cudaEvent_t ev_fork = nullptr, ev_z = nullptr, ev_join = nullptr,
                       ev_csr1 = nullptr;
    if (!s2) {
        cudaStreamCreateWithFlags(&s2, cudaStreamNonBlocking);
        cudaStreamCreateWithFlags(&s3, cudaStreamNonBlocking);
        cudaEventCreateWithFlags(&ev_fork, cudaEventDisableTiming);
        cudaEventCreateWithFlags(&ev_z, cudaEventDisableTiming);
        cudaEventCreateWithFlags(&ev_join, cudaEventDisableTiming);
        cudaEventCreateWithFlags(&ev_csr1, cudaEventDisableTiming);
        cudaFuncSetAttribute(gemm_kernel,
                             cudaFuncAttributeMaxDynamicSharedMemorySize, SMEM_TOTAL);
    }

    cudaEventRecord(ev_fork, 0);
    cudaStreamWaitEvent(s2, ev_fork, 0);
    cudaStreamWaitEvent(s3, ev_fork, 0);

    // -- s2: GEMM path --
    wprep_kernel<<<(IN_CH * HO + 255) / 256, 256, 0, s2>>>(W);
    gemm_kernel<<<(N_NODES + 63) / 64, 128, SMEM_TOTAL, s2>>>(x, att);
    cudaEventRecord(ev_join, s2);

    // -- main: zero+detect, then CSR pipeline 0 --
    zero_detect_kernel<<<(N_NODES + 255) / 256, 256>>>((const unsigned int*)eidx);
    cudaEventRecord(ev_z, 0);

    hist_kernel<<<(E_HALF + 255) / 256, 256>>>(eidx, 0);
    scan1_kernel<<<SCAN_NB, SCAN_B>>>(0);
    scan3_kernel<<<SCAN_NB, SCAN_B>>>(0);
    scatter_kernel<<<(E_HALF + 255) / 256, 256>>>(eidx, 0);

    // -- s3: CSR pipeline 1 (concurrent) --
    cudaStreamWaitEvent(s3, ev_z, 0);
    hist_kernel<<<(E_HALF + 255) / 256, 256, 0, s3>>>(eidx, 1);
    scan1_kernel<<<SCAN_NB, SCAN_B, 0, s3>>>(1);
    scan3_kernel<<<SCAN_NB, SCAN_B, 0, s3>>>(1);
    scatter_kernel<<<(E_HALF + 255) / 256, 256, 0, s3>>>(eidx, 1);
    cudaEventRecord(ev_csr1, s3);

    // join: gather needs both CSR halves + gemm
    cudaStreamWaitEvent(0, ev_csr1, 0);
    cudaStreamWaitEvent(0, ev_join, 0);
    gather_kernel<<<((N_NODES + 1) / 2 * 32 + 255) / 256, 256>>>(out, bias);
}

// round 16
// speedup vs baseline: 1.0166x; 1.0166x over previous
#include <cuda_runtime.h>
#include <cuda_bf16.h>
#include <cuda_fp16.h>
#include <cstdint>

#define N_NODES 100000
#define N_EDGES 1600000
#define IN_CH 128
#define HEADS 4
#define OUT_CH 32
#define HO 128
#define NEG_SLOPE 0.2f
#define EPS 1e-10f

#define SCAN_B 512
#define SCAN_NB ((N_NODES + SCAN_B - 1) / SCAN_B)   // 196

// ---------------- scratch ----------------
__device__ __align__(16) __half g_h16[(size_t)N_NODES * HO];   // 25.6 MB
__device__ __align__(16) float g_ssrc[(size_t)N_NODES * HEADS];
__device__ __align__(16) float g_stgt[(size_t)N_NODES * HEADS];
__device__ __align__(16) __half g_wt16[IN_CH * HO];            // W^T fp16 [n][k]
__device__ int g_deg[N_NODES];
__device__ int g_off[N_NODES];
__device__ int g_cursor[N_NODES];
__device__ int g_bsum[SCAN_NB];
__device__ int g_esrc[N_EDGES];
__device__ int g_etgt[N_EDGES];
__device__ int g_idx64;

__device__ __forceinline__ int load_idx(const void* eidx, int i) {
    if (g_idx64) return (int)((const long long*)eidx)[i];
    return ((const int*)eidx)[i];
}

// ---------------- zero degree + dtype detection (merged) ----------------
__global__ void zero_detect_kernel(const unsigned int* __restrict__ e) {
    int i = blockIdx.x * blockDim.x + threadIdx.x;
    if (i < N_NODES) g_deg[i] = 0;
    if (blockIdx.x == 0) {
        __shared__ int any;
        if (threadIdx.x == 0) any = 0;
        __syncthreads();
        unsigned int v = 0;
        for (int k = threadIdx.x; k < 1024; k += blockDim.x) v |= e[2 * k + 1];
        if (v) any = 1;
        __syncthreads();
        if (threadIdx.x == 0) g_idx64 = (any == 0) ? 1 : 0;
    }
}

// ---------------- histogram: 4 edges/thread, MLP-4 ----------------
__global__ __launch_bounds__(256) void hist_kernel(const void* __restrict__ eidx) {
    int e0 = blockIdx.x * 1024 + threadIdx.x;
    int t0 = -1, t1 = -1, t2 = -1, t3 = -1;
    if (g_idx64) {
        const long long* p = (const long long*)eidx + N_EDGES;
        if (e0 < N_EDGES) t0 = (int)p[e0];
        if (e0 + 256 < N_EDGES) t1 = (int)p[e0 + 256];
        if (e0 + 512 < N_EDGES) t2 = (int)p[e0 + 512];
        if (e0 + 768 < N_EDGES) t3 = (int)p[e0 + 768];
    } else {
        const int* p = (const int*)eidx + N_EDGES;
        if (e0 < N_EDGES) t0 = p[e0];
        if (e0 + 256 < N_EDGES) t1 = p[e0 + 256];
        if (e0 + 512 < N_EDGES) t2 = p[e0 + 512];
        if (e0 + 768 < N_EDGES) t3 = p[e0 + 768];
    }
    if (t0 >= 0) { g_etgt[e0] = t0; atomicAdd(&g_deg[t0], 1); }
    if (t1 >= 0) { g_etgt[e0 + 256] = t1; atomicAdd(&g_deg[t1], 1); }
    if (t2 >= 0) { g_etgt[e0 + 512] = t2; atomicAdd(&g_deg[t2], 1); }
    if (t3 >= 0) { g_etgt[e0 + 768] = t3; atomicAdd(&g_deg[t3], 1); }
}

// ---------------- scan1: shuffle-based block scan ----------------
__global__ __launch_bounds__(SCAN_B) void scan1_kernel() {
    __shared__ int warp_sums[16];
    int t = threadIdx.x;
    int lane = t & 31;
    int w = t >> 5;
    int i = blockIdx.x * SCAN_B + t;
    int v = (i < N_NODES) ? g_deg[i] : 0;
    int inc = v;
#pragma unroll
    for (int off = 1; off < 32; off <<= 1) {
        int n = __shfl_up_sync(0xffffffffu, inc, off);
        if (lane >= off) inc += n;
    }
    if (lane == 31) warp_sums[w] = inc;
    __syncthreads();
    if (w == 0) {
        int s = (lane < 16) ? warp_sums[lane] : 0;
#pragma unroll
        for (int off = 1; off < 16; off <<= 1) {
            int n = __shfl_up_sync(0xffffffffu, s, off);
            if (lane >= off) s += n;
        }
        if (lane < 16) warp_sums[lane] = s;
    }
    __syncthreads();
    int base = (w > 0) ? warp_sums[w - 1] : 0;
    if (i < N_NODES) g_off[i] = base + inc - v;
    if (t == SCAN_B - 1) g_bsum[blockIdx.x] = base + inc;
}

// ---------------- scan3: per-block redundant prefix of block sums ----------------
__global__ __launch_bounds__(SCAN_B) void scan3_kernel() {
    __shared__ int s_red[16];
    __shared__ int s_base;
    int bid = blockIdx.x;
    int t = threadIdx.x;
    int lane = t & 31;
    int w = t >> 5;
    int v = (t < bid) ? g_bsum[t] : 0;
#pragma unroll
    for (int off = 16; off > 0; off >>= 1) v += __shfl_xor_sync(0xffffffffu, v, off);
    if (lane == 0) s_red[w] = v;
    __syncthreads();
    if (t == 0) {
        int s = 0;
#pragma unroll
        for (int k = 0; k < 16; k++) s += s_red[k];
        s_base = s;
    }
    __syncthreads();
    int i = bid * SCAN_B + t;
    if (i < N_NODES) {
        int o = g_off[i] + s_base;
        g_off[i] = o;
        g_cursor[i] = o;
    }
}

// ---------------- scatter: 4 edges/thread, MLP-4 ----------------
__global__ __launch_bounds__(256) void scatter_kernel(const void* __restrict__ eidx) {
    int e0 = blockIdx.x * 1024 + threadIdx.x;
    int s0 = 0, s1 = 0, s2 = 0, s3 = 0;
    int n0 = (e0 < N_EDGES), n1 = (e0 + 256 < N_EDGES),
        n2 = (e0 + 512 < N_EDGES), n3 = (e0 + 768 < N_EDGES);
    if (g_idx64) {
        const long long* p = (const long long*)eidx;
        if (n0) s0 = (int)p[e0];
        if (n1) s1 = (int)p[e0 + 256];
        if (n2) s2 = (int)p[e0 + 512];
        if (n3) s3 = (int)p[e0 + 768];
    } else {
        const int* p = (const int*)eidx;
        if (n0) s0 = p[e0];
        if (n1) s1 = p[e0 + 256];
        if (n2) s2 = p[e0 + 512];
        if (n3) s3 = p[e0 + 768];
    }
    int t0 = 0, t1 = 0, t2 = 0, t3 = 0;
    if (n0) t0 = g_etgt[e0];
    if (n1) t1 = g_etgt[e0 + 256];
    if (n2) t2 = g_etgt[e0 + 512];
    if (n3) t3 = g_etgt[e0 + 768];
    int q0 = 0, q1 = 0, q2 = 0, q3 = 0;
    if (n0) q0 = atomicAdd(&g_cursor[t0], 1);
    if (n1) q1 = atomicAdd(&g_cursor[t1], 1);
    if (n2) q2 = atomicAdd(&g_cursor[t2], 1);
    if (n3) q3 = atomicAdd(&g_cursor[t3], 1);
    if (n0) g_esrc[q0] = s0;
    if (n1) g_esrc[q1] = s1;
    if (n2) g_esrc[q2] = s2;
    if (n3) g_esrc[q3] = s3;
}

// ---------------- W prep: g_wt16[n][k] = fp16(W[k][n]) ----------------
__global__ __launch_bounds__(256) void wprep_kernel(const float* __restrict__ W) {
    int i = blockIdx.x * blockDim.x + threadIdx.x;
    if (i >= IN_CH * HO) return;
    int n = i & 127;
    int k = i >> 7;
    g_wt16[n * IN_CH + k] = __float2half(W[k * HO + n]);
}

// ---------------- HMMA GEMM + fused scores ----------------
#define A_STRIDE 136
#define W_STRIDE 136
#define ACC_STRIDE 132
#define SMEM_A_BYTES (64 * A_STRIDE * 2)            // 17408
#define SMEM_W_BYTES (128 * W_STRIDE * 2)           // 34816
#define SMEM_TOTAL (SMEM_A_BYTES + SMEM_W_BYTES)    // 52224

extern __shared__ char dsm[];

__global__ __launch_bounds__(128) void gemm_kernel(
    const float* __restrict__ x, const float* __restrict__ att) {
    __shared__ float s_att[HEADS * 2 * OUT_CH];     // 256

    const int tid = threadIdx.x;
    const int warpid = tid >> 5;
    const int lane = tid & 31;
    const int g = lane >> 2;
    const int tg = lane & 3;
    const int row0 = blockIdx.x * 64;

    __half* As = (__half*)dsm;
    __half* Ws = (__half*)(dsm + SMEM_A_BYTES);

    s_att[tid] = att[tid];
    s_att[tid + 128] = att[tid + 128];

    {
        const uint4* wsrc = (const uint4*)g_wt16;
#pragma unroll
        for (int j = 0; j < 16; j++) {
            int i = tid + j * 128;
            int row = i >> 4;
            int c8 = i & 15;
            *(uint4*)&Ws[row * W_STRIDE + c8 * 8] = wsrc[i];
        }
    }

    {
#pragma unroll
        for (int j = 0; j < 16; j++) {
            int i = tid + j * 128;
            int row = i >> 5;
            int c4 = i & 31;
            int grow = row0 + row;
            float4 v = make_float4(0.f, 0.f, 0.f, 0.f);
            if (grow < N_NODES)
                v = ((const float4*)x)[(size_t)grow * (IN_CH / 4) + c4];
            __half2 h0 = __float22half2_rn(make_float2(v.x, v.y));
            __half2 h1 = __float22half2_rn(make_float2(v.z, v.w));
            uint2 p;
            p.x = *(unsigned int*)&h0;
            p.y = *(unsigned int*)&h1;
            *(uint2*)&As[row * A_STRIDE + c4 * 4] = p;
        }
    }
    __syncthreads();

    float acc[16][4];
#pragma unroll
    for (int nt = 0; nt < 16; nt++)
#pragma unroll
        for (int j = 0; j < 4; j++) acc[nt][j] = 0.f;

    const int arow = warpid * 16 + g;
#pragma unroll
    for (int ks = 0; ks < 8; ks++) {
        int kcol = ks * 16 + tg * 2;
        uint32_t a0 = *(uint32_t*)&As[arow * A_STRIDE + kcol];
        uint32_t a1 = *(uint32_t*)&As[(arow + 8) * A_STRIDE + kcol];
        uint32_t a2 = *(uint32_t*)&As[arow * A_STRIDE + kcol + 8];
        uint32_t a3 = *(uint32_t*)&As[(arow + 8) * A_STRIDE + kcol + 8];
#pragma unroll
        for (int nt = 0; nt < 16; nt++) {
            int n = nt * 8 + g;
            uint32_t b0 = *(uint32_t*)&Ws[n * W_STRIDE + kcol];
            uint32_t b1 = *(uint32_t*)&Ws[n * W_STRIDE + kcol + 8];
            asm volatile(
                "mma.sync.aligned.m16n8k16.row.col.f32.f16.f16.f32 "
                "{%0,%1,%2,%3}, {%4,%5,%6,%7}, {%8,%9}, {%0,%1,%2,%3};"
                : "+f"(acc[nt][0]), "+f"(acc[nt][1]),
                  "+f"(acc[nt][2]), "+f"(acc[nt][3])
                : "r"(a0), "r"(a1), "r"(a2), "r"(a3), "r"(b0), "r"(b1));
        }
    }
    __syncthreads();

    float* sAcc = (float*)dsm;
    {
        int r0 = warpid * 16 + g;
#pragma unroll
        for (int nt = 0; nt < 16; nt++) {
            int col = nt * 8 + tg * 2;
            *(float2*)&sAcc[r0 * ACC_STRIDE + col] =
                make_float2(acc[nt][0], acc[nt][1]);
            *(float2*)&sAcc[(r0 + 8) * ACC_STRIDE + col] =
                make_float2(acc[nt][2], acc[nt][3]);
        }
    }
    __syncwarp();

    const int head = lane >> 3;
    const int o0 = (lane & 7) * 4;
    float as0 = s_att[head * 64 + o0], as1 = s_att[head * 64 + o0 + 1],
          as2 = s_att[head * 64 + o0 + 2], as3 = s_att[head * 64 + o0 + 3];
    float at0 = s_att[head * 64 + 32 + o0], at1 = s_att[head * 64 + 32 + o0 + 1],
          at2 = s_att[head * 64 + 32 + o0 + 2], at3 = s_att[head * 64 + 32 + o0 + 3];

#pragma unroll
    for (int rr = 0; rr < 16; rr++) {
        int row = warpid * 16 + rr;
        int grow = row0 + row;
        float4 c = *(float4*)&sAcc[row * ACC_STRIDE + lane * 4];
        if (grow < N_NODES) {
            __half2 t0 = __float22half2_rn(make_float2(c.x, c.y));
            __half2 t1 = __float22half2_rn(make_float2(c.z, c.w));
            uint2 p;
            p.x = *(unsigned int*)&t0;
            p.y = *(unsigned int*)&t1;
            ((uint2*)(g_h16 + (size_t)grow * HO))[lane] = p;
        }
        float ps = c.x * as0 + c.y * as1 + c.z * as2 + c.w * as3;
        float pt = c.x * at0 + c.y * at1 + c.z * at2 + c.w * at3;
#pragma unroll
        for (int off = 4; off > 0; off >>= 1) {
            ps += __shfl_xor_sync(0xffffffffu, ps, off);
            pt += __shfl_xor_sync(0xffffffffu, pt, off);
        }
        if ((lane & 7) == 0 && grow < N_NODES) {
            g_ssrc[grow * HEADS + head] = ps;
            g_stgt[grow * HEADS + head] = pt;
        }
    }
}

// ---------------- gather-reduce: 2 nodes per warp, 16 lanes/node (R14) ----------------
__global__ __launch_bounds__(256) void gather_kernel(
    float* __restrict__ out, const float* __restrict__ bias) {
    int warp = (blockIdx.x * blockDim.x + threadIdx.x) >> 5;
    int lane = threadIdx.x & 31;
    int grp = lane >> 4;
    int li = lane & 15;
    int node = warp * 2 + grp;
    if (node >= N_NODES) return;
    int head = li >> 2;

    int start = g_off[node];
    int cnt = g_deg[node];
    float st = g_stgt[node * HEADS + head];

    float4 accA = make_float4(0.f, 0.f, 0.f, 0.f);
    float4 accB = make_float4(0.f, 0.f, 0.f, 0.f);
    float den = 0.f;

    const uint4* h16 = (const uint4*)g_h16;
    int j = 0;
    for (; j + 2 <= cnt; j += 2) {
        int s0 = g_esrc[start + j];
        int s1 = g_esrc[start + j + 1];
        float sc0 = g_ssrc[s0 * HEADS + head] + st;
        float sc1 = g_ssrc[s1 * HEADS + head] + st;
        uint4 v0 = h16[(size_t)s0 * 16 + li];
        uint4 v1 = h16[(size_t)s1 * 16 + li];
        float lr0 = sc0 > 0.f ? sc0 : NEG_SLOPE * sc0;
        float lr1 = sc1 > 0.f ? sc1 : NEG_SLOPE * sc1;
        float w0 = __expf(-lr0);
        float w1 = __expf(-lr1);
        float2 p00 = __half22float2(*(const __half2*)&v0.x);
        float2 p01 = __half22float2(*(const __half2*)&v0.y);
        float2 p02 = __half22float2(*(const __half2*)&v0.z);
        float2 p03 = __half22float2(*(const __half2*)&v0.w);
        float2 p10 = __half22float2(*(const __half2*)&v1.x);
        float2 p11 = __half22float2(*(const __half2*)&v1.y);
        float2 p12 = __half22float2(*(const __half2*)&v1.z);
        float2 p13 = __half22float2(*(const __half2*)&v1.w);
        accA.x += w0 * p00.x + w1 * p10.x;
        accA.y += w0 * p00.y + w1 * p10.y;
        accA.z += w0 * p01.x + w1 * p11.x;
        accA.w += w0 * p01.y + w1 * p11.y;
        accB.x += w0 * p02.x + w1 * p12.x;
        accB.y += w0 * p02.y + w1 * p12.y;
        accB.z += w0 * p03.x + w1 * p13.x;
        accB.w += w0 * p03.y + w1 * p13.y;
        den += w0 + w1;
    }
    if (j < cnt) {
        int s0 = g_esrc[start + j];
        float sc0 = g_ssrc[s0 * HEADS + head] + st;
        uint4 v0 = h16[(size_t)s0 * 16 + li];
        float lr0 = sc0 > 0.f ? sc0 : NEG_SLOPE * sc0;
        float w0 = __expf(-lr0);
        float2 p00 = __half22float2(*(const __half2*)&v0.x);
        float2 p01 = __half22float2(*(const __half2*)&v0.y);
        float2 p02 = __half22float2(*(const __half2*)&v0.z);
        float2 p03 = __half22float2(*(const __half2*)&v0.w);
        accA.x += w0 * p00.x;
        accA.y += w0 * p00.y;
        accA.z += w0 * p01.x;
        accA.w += w0 * p01.y;
        accB.x += w0 * p02.x;
        accB.y += w0 * p02.y;
        accB.z += w0 * p03.x;
        accB.w += w0 * p03.y;
        den += w0;
    }

    float d = den > EPS ? den : EPS;
    float inv = 1.0f / d;
    float4 b0 = ((const float4*)bias)[li * 2];
    float4 b1 = ((const float4*)bias)[li * 2 + 1];
    float4 o0, o1;
    o0.x = accA.x * inv + b0.x;
    o0.y = accA.y * inv + b0.y;
    o0.z = accA.z * inv + b0.z;
    o0.w = accA.w * inv + b0.w;
    o1.x = accB.x * inv + b1.x;
    o1.y = accB.y * inv + b1.y;
    o1.z = accB.z * inv + b1.z;
    o1.w = accB.w * inv + b1.w;
    float4* op = (float4*)(out + (size_t)node * HO) + li * 2;
    op[0] = o0;
    op[1] = o1;
}

extern "C" void kernel_launch(void* const* d_in, const int* in_sizes, int n_in,
                              void* d_out, int out_size) {
    const float* x = (const float*)d_in[0];
    const void* eidx = d_in[1];
    const float* W = (const float*)d_in[2];
    const float* att = (const float*)d_in[3];
    const float* bias = (const float*)d_in[4];
    float* out = (float*)d_out;

    static cudaStream_t s2 = nullptr;
    static cudaEvent_t ev_fork = nullptr, ev_join = nullptr;
    if (!s2) {
        cudaStreamCreateWithFlags(&s2, cudaStreamNonBlocking);
        cudaEventCreateWithFlags(&ev_fork, cudaEventDisableTiming);
        cudaEventCreateWithFlags(&ev_join, cudaEventDisableTiming);
        cudaFuncSetAttribute(gemm_kernel,
                             cudaFuncAttributeMaxDynamicSharedMemorySize, SMEM_TOTAL);
    }

    cudaEventRecord(ev_fork, 0);
    cudaStreamWaitEvent(s2, ev_fork, 0);

    // -- s2: GEMM path --
    wprep_kernel<<<(IN_CH * HO + 255) / 256, 256, 0, s2>>>(W);
    gemm_kernel<<<(N_NODES + 63) / 64, 128, SMEM_TOTAL, s2>>>(x, att);
    cudaEventRecord(ev_join, s2);

    // -- default stream: CSR build path --
    zero_detect_kernel<<<(N_NODES + 255) / 256, 256>>>((const unsigned int*)eidx);
    hist_kernel<<<(N_EDGES + 1023) / 1024, 256>>>(eidx);
    scan1_kernel<<<SCAN_NB, SCAN_B>>>();
    scan3_kernel<<<SCAN_NB, SCAN_B>>>();
    scatter_kernel<<<(N_EDGES + 1023) / 1024, 256>>>(eidx);

    cudaStreamWaitEvent(0, ev_join, 0);
    gather_kernel<<<((N_NODES + 1) / 2 * 32 + 255) / 256, 256>>>(out, bias);
}

// round 17
// speedup vs baseline: 1.0519x; 1.0347x over previous
#include <cuda_runtime.h>
#include <cuda_bf16.h>
#include <cuda_fp16.h>
#include <cstdint>

#define N_NODES 100000
#define N_EDGES 1600000
#define IN_CH 128
#define HEADS 4
#define OUT_CH 32
#define HO 128
#define NEG_SLOPE 0.2f
#define EPS 1e-10f

#define SCAN_B 512
#define SCAN_NB ((N_NODES + SCAN_B - 1) / SCAN_B)   // 196

// ---------------- scratch ----------------
__device__ __align__(16) __half g_h16[(size_t)N_NODES * HO];   // 25.6 MB
__device__ __align__(16) float g_ssrc[(size_t)N_NODES * HEADS];
__device__ __align__(16) float g_stgt[(size_t)N_NODES * HEADS];
__device__ __align__(16) __half g_wt16[IN_CH * HO];            // W^T fp16 [n][k]
__device__ int g_deg[N_NODES];
__device__ int g_off[N_NODES];
__device__ int g_cursor[N_NODES];
__device__ int g_bsum[SCAN_NB];
__device__ int g_esrc[N_EDGES];
__device__ int g_etgt[N_EDGES];
__device__ int g_idx64;

__device__ __forceinline__ int load_idx(const void* eidx, int i) {
    if (g_idx64) return (int)((const long long*)eidx)[i];
    return ((const int*)eidx)[i];
}

// ---------------- zero degree + dtype detection (merged) ----------------
__global__ void zero_detect_kernel(const unsigned int* __restrict__ e) {
    int i = blockIdx.x * blockDim.x + threadIdx.x;
    if (i < N_NODES) g_deg[i] = 0;
    if (blockIdx.x == 0) {
        __shared__ int any;
        if (threadIdx.x == 0) any = 0;
        __syncthreads();
        unsigned int v = 0;
        for (int k = threadIdx.x; k < 1024; k += blockDim.x) v |= e[2 * k + 1];
        if (v) any = 1;
        __syncthreads();
        if (threadIdx.x == 0) g_idx64 = (any == 0) ? 1 : 0;
    }
}

// ---------------- histogram: 4 edges/thread, MLP-4 (proven R16) ----------------
__global__ __launch_bounds__(256) void hist_kernel(const void* __restrict__ eidx) {
    int e0 = blockIdx.x * 1024 + threadIdx.x;
    int t0 = -1, t1 = -1, t2 = -1, t3 = -1;
    if (g_idx64) {
        const long long* p = (const long long*)eidx + N_EDGES;
        if (e0 < N_EDGES) t0 = (int)p[e0];
        if (e0 + 256 < N_EDGES) t1 = (int)p[e0 + 256];
        if (e0 + 512 < N_EDGES) t2 = (int)p[e0 + 512];
        if (e0 + 768 < N_EDGES) t3 = (int)p[e0 + 768];
    } else {
        const int* p = (const int*)eidx + N_EDGES;
        if (e0 < N_EDGES) t0 = p[e0];
        if (e0 + 256 < N_EDGES) t1 = p[e0 + 256];
        if (e0 + 512 < N_EDGES) t2 = p[e0 + 512];
        if (e0 + 768 < N_EDGES) t3 = p[e0 + 768];
    }
    if (t0 >= 0) { g_etgt[e0] = t0; atomicAdd(&g_deg[t0], 1); }
    if (t1 >= 0) { g_etgt[e0 + 256] = t1; atomicAdd(&g_deg[t1], 1); }
    if (t2 >= 0) { g_etgt[e0 + 512] = t2; atomicAdd(&g_deg[t2], 1); }
    if (t3 >= 0) { g_etgt[e0 + 768] = t3; atomicAdd(&g_deg[t3], 1); }
}

// ---------------- scan1: shuffle-based block scan ----------------
__global__ __launch_bounds__(SCAN_B) void scan1_kernel() {
    __shared__ int warp_sums[16];
    int t = threadIdx.x;
    int lane = t & 31;
    int w = t >> 5;
    int i = blockIdx.x * SCAN_B + t;
    int v = (i < N_NODES) ? g_deg[i] : 0;
    int inc = v;
#pragma unroll
    for (int off = 1; off < 32; off <<= 1) {
        int n = __shfl_up_sync(0xffffffffu, inc, off);
        if (lane >= off) inc += n;
    }
    if (lane == 31) warp_sums[w] = inc;
    __syncthreads();
    if (w == 0) {
        int s = (lane < 16) ? warp_sums[lane] : 0;
#pragma unroll
        for (int off = 1; off < 16; off <<= 1) {
            int n = __shfl_up_sync(0xffffffffu, s, off);
            if (lane >= off) s += n;
        }
        if (lane < 16) warp_sums[lane] = s;
    }
    __syncthreads();
    int base = (w > 0) ? warp_sums[w - 1] : 0;
    if (i < N_NODES) g_off[i] = base + inc - v;
    if (t == SCAN_B - 1) g_bsum[blockIdx.x] = base + inc;
}

// ---------------- scan3: per-block redundant prefix of block sums ----------------
__global__ __launch_bounds__(SCAN_B) void scan3_kernel() {
    __shared__ int s_red[16];
    __shared__ int s_base;
    int bid = blockIdx.x;
    int t = threadIdx.x;
    int lane = t & 31;
    int w = t >> 5;
    int v = (t < bid) ? g_bsum[t] : 0;
#pragma unroll
    for (int off = 16; off > 0; off >>= 1) v += __shfl_xor_sync(0xffffffffu, v, off);
    if (lane == 0) s_red[w] = v;
    __syncthreads();
    if (t == 0) {
        int s = 0;
#pragma unroll
        for (int k = 0; k < 16; k++) s += s_red[k];
        s_base = s;
    }
    __syncthreads();
    int i = bid * SCAN_B + t;
    if (i < N_NODES) {
        int o = g_off[i] + s_base;
        g_off[i] = o;
        g_cursor[i] = o;
    }
}

// ---------------- scatter edges into CSR buckets (R14 simple form) ----------------
__global__ __launch_bounds__(256) void scatter_kernel(const void* __restrict__ eidx) {
    int e = blockIdx.x * blockDim.x + threadIdx.x;
    if (e >= N_EDGES) return;
    int src = load_idx(eidx, e);
    int tgt = g_etgt[e];
    int slot = atomicAdd(&g_cursor[tgt], 1);
    g_esrc[slot] = src;
}

// ---------------- W prep: g_wt16[n][k] = fp16(W[k][n]) ----------------
__global__ __launch_bounds__(256) void wprep_kernel(const float* __restrict__ W) {
    int i = blockIdx.x * blockDim.x + threadIdx.x;
    if (i >= IN_CH * HO) return;
    int n = i & 127;
    int k = i >> 7;
    g_wt16[n * IN_CH + k] = __float2half(W[k * HO + n]);
}

// ---------------- HMMA GEMM + fused scores ----------------
#define A_STRIDE 136
#define W_STRIDE 136
#define ACC_STRIDE 132
#define SMEM_A_BYTES (64 * A_STRIDE * 2)            // 17408
#define SMEM_W_BYTES (128 * W_STRIDE * 2)           // 34816
#define SMEM_TOTAL (SMEM_A_BYTES + SMEM_W_BYTES)    // 52224

extern __shared__ char dsm[];

__global__ __launch_bounds__(128) void gemm_kernel(
    const float* __restrict__ x, const float* __restrict__ att) {
    __shared__ float s_att[HEADS * 2 * OUT_CH];     // 256

    const int tid = threadIdx.x;
    const int warpid = tid >> 5;
    const int lane = tid & 31;
    const int g = lane >> 2;
    const int tg = lane & 3;
    const int row0 = blockIdx.x * 64;

    __half* As = (__half*)dsm;
    __half* Ws = (__half*)(dsm + SMEM_A_BYTES);

    s_att[tid] = att[tid];
    s_att[tid + 128] = att[tid + 128];

    {
        const uint4* wsrc = (const uint4*)g_wt16;
#pragma unroll
        for (int j = 0; j < 16; j++) {
            int i = tid + j * 128;
            int row = i >> 4;
            int c8 = i & 15;
            *(uint4*)&Ws[row * W_STRIDE + c8 * 8] = wsrc[i];
        }
    }

    {
#pragma unroll
        for (int j = 0; j < 16; j++) {
            int i = tid + j * 128;
            int row = i >> 5;
            int c4 = i & 31;
            int grow = row0 + row;
            float4 v = make_float4(0.f, 0.f, 0.f, 0.f);
            if (grow < N_NODES)
                v = ((const float4*)x)[(size_t)grow * (IN_CH / 4) + c4];
            __half2 h0 = __float22half2_rn(make_float2(v.x, v.y));
            __half2 h1 = __float22half2_rn(make_float2(v.z, v.w));
            uint2 p;
            p.x = *(unsigned int*)&h0;
            p.y = *(unsigned int*)&h1;
            *(uint2*)&As[row * A_STRIDE + c4 * 4] = p;
        }
    }
    __syncthreads();

    float acc[16][4];
#pragma unroll
    for (int nt = 0; nt < 16; nt++)
#pragma unroll
        for (int j = 0; j < 4; j++) acc[nt][j] = 0.f;

    const int arow = warpid * 16 + g;
#pragma unroll
    for (int ks = 0; ks < 8; ks++) {
        int kcol = ks * 16 + tg * 2;
        uint32_t a0 = *(uint32_t*)&As[arow * A_STRIDE + kcol];
        uint32_t a1 = *(uint32_t*)&As[(arow + 8) * A_STRIDE + kcol];
        uint32_t a2 = *(uint32_t*)&As[arow * A_STRIDE + kcol + 8];
        uint32_t a3 = *(uint32_t*)&As[(arow + 8) * A_STRIDE + kcol + 8];
#pragma unroll
        for (int nt = 0; nt < 16; nt++) {
            int n = nt * 8 + g;
            uint32_t b0 = *(uint32_t*)&Ws[n * W_STRIDE + kcol];
            uint32_t b1 = *(uint32_t*)&Ws[n * W_STRIDE + kcol + 8];
            asm volatile(
                "mma.sync.aligned.m16n8k16.row.col.f32.f16.f16.f32 "
                "{%0,%1,%2,%3}, {%4,%5,%6,%7}, {%8,%9}, {%0,%1,%2,%3};"
                : "+f"(acc[nt][0]), "+f"(acc[nt][1]),
                  "+f"(acc[nt][2]), "+f"(acc[nt][3])
                : "r"(a0), "r"(a1), "r"(a2), "r"(a3), "r"(b0), "r"(b1));
        }
    }
    __syncthreads();

    float* sAcc = (float*)dsm;
    {
        int r0 = warpid * 16 + g;
#pragma unroll
        for (int nt = 0; nt < 16; nt++) {
            int col = nt * 8 + tg * 2;
            *(float2*)&sAcc[r0 * ACC_STRIDE + col] =
                make_float2(acc[nt][0], acc[nt][1]);
            *(float2*)&sAcc[(r0 + 8) * ACC_STRIDE + col] =
                make_float2(acc[nt][2], acc[nt][3]);
        }
    }
    __syncwarp();

    const int head = lane >> 3;
    const int o0 = (lane & 7) * 4;
    float as0 = s_att[head * 64 + o0], as1 = s_att[head * 64 + o0 + 1],
          as2 = s_att[head * 64 + o0 + 2], as3 = s_att[head * 64 + o0 + 3];
    float at0 = s_att[head * 64 + 32 + o0], at1 = s_att[head * 64 + 32 + o0 + 1],
          at2 = s_att[head * 64 + 32 + o0 + 2], at3 = s_att[head * 64 + 32 + o0 + 3];

#pragma unroll
    for (int rr = 0; rr < 16; rr++) {
        int row = warpid * 16 + rr;
        int grow = row0 + row;
        float4 c = *(float4*)&sAcc[row * ACC_STRIDE + lane * 4];
        if (grow < N_NODES) {
            __half2 t0 = __float22half2_rn(make_float2(c.x, c.y));
            __half2 t1 = __float22half2_rn(make_float2(c.z, c.w));
            uint2 p;
            p.x = *(unsigned int*)&t0;
            p.y = *(unsigned int*)&t1;
            ((uint2*)(g_h16 + (size_t)grow * HO))[lane] = p;
        }
        float ps = c.x * as0 + c.y * as1 + c.z * as2 + c.w * as3;
        float pt = c.x * at0 + c.y * at1 + c.z * at2 + c.w * at3;
#pragma unroll
        for (int off = 4; off > 0; off >>= 1) {
            ps += __shfl_xor_sync(0xffffffffu, ps, off);
            pt += __shfl_xor_sync(0xffffffffu, pt, off);
        }
        if ((lane & 7) == 0 && grow < N_NODES) {
            g_ssrc[grow * HEADS + head] = ps;
            g_stgt[grow * HEADS + head] = pt;
        }
    }
}

// ---------------- gather-reduce: 2 nodes/warp, NC loads for read-only data ----------------
__device__ __forceinline__ uint4 ldg_nc_u4(const uint4* p) {
    uint4 v;
    asm volatile("ld.global.nc.v4.u32 {%0, %1, %2, %3}, [%4];"
                 : "=r"(v.x), "=r"(v.y), "=r"(v.z), "=r"(v.w) : "l"(p));
    return v;
}

__global__ __launch_bounds__(256) void gather_kernel(
    float* __restrict__ out, const float* __restrict__ bias) {
    int warp = (blockIdx.x * blockDim.x + threadIdx.x) >> 5;
    int lane = threadIdx.x & 31;
    int grp = lane >> 4;
    int li = lane & 15;
    int node = warp * 2 + grp;
    if (node >= N_NODES) return;
    int head = li >> 2;

    int start = g_off[node];
    int cnt = g_deg[node];
    float st = g_stgt[node * HEADS + head];

    float4 accA = make_float4(0.f, 0.f, 0.f, 0.f);
    float4 accB = make_float4(0.f, 0.f, 0.f, 0.f);
    float den = 0.f;

    const uint4* h16 = (const uint4*)g_h16;
    int j = 0;
    for (; j + 2 <= cnt; j += 2) {
        int s0 = __ldg(&g_esrc[start + j]);
        int s1 = __ldg(&g_esrc[start + j + 1]);
        float sc0 = __ldg(&g_ssrc[s0 * HEADS + head]) + st;
        float sc1 = __ldg(&g_ssrc[s1 * HEADS + head]) + st;
        uint4 v0 = ldg_nc_u4(h16 + (size_t)s0 * 16 + li);
        uint4 v1 = ldg_nc_u4(h16 + (size_t)s1 * 16 + li);
        float lr0 = sc0 > 0.f ? sc0 : NEG_SLOPE * sc0;
        float lr1 = sc1 > 0.f ? sc1 : NEG_SLOPE * sc1;
        float w0 = __expf(-lr0);
        float w1 = __expf(-lr1);
        float2 p00 = __half22float2(*(const __half2*)&v0.x);
        float2 p01 = __half22float2(*(const __half2*)&v0.y);
        float2 p02 = __half22float2(*(const __half2*)&v0.z);
        float2 p03 = __half22float2(*(const __half2*)&v0.w);
        float2 p10 = __half22float2(*(const __half2*)&v1.x);
        float2 p11 = __half22float2(*(const __half2*)&v1.y);
        float2 p12 = __half22float2(*(const __half2*)&v1.z);
        float2 p13 = __half22float2(*(const __half2*)&v1.w);
        accA.x += w0 * p00.x + w1 * p10.x;
        accA.y += w0 * p00.y + w1 * p10.y;
        accA.z += w0 * p01.x + w1 * p11.x;
        accA.w += w0 * p01.y + w1 * p11.y;
        accB.x += w0 * p02.x + w1 * p12.x;
        accB.y += w0 * p02.y + w1 * p12.y;
        accB.z += w0 * p03.x + w1 * p13.x;
        accB.w += w0 * p03.y + w1 * p13.y;
        den += w0 + w1;
    }
    if (j < cnt) {
        int s0 = __ldg(&g_esrc[start + j]);
        float sc0 = __ldg(&g_ssrc[s0 * HEADS + head]) + st;
        uint4 v0 = ldg_nc_u4(h16 + (size_t)s0 * 16 + li);
        float lr0 = sc0 > 0.f ? sc0 : NEG_SLOPE * sc0;
        float w0 = __expf(-lr0);
        float2 p00 = __half22float2(*(const __half2*)&v0.x);
        float2 p01 = __half22float2(*(const __half2*)&v0.y);
        float2 p02 = __half22float2(*(const __half2*)&v0.z);
        float2 p03 = __half22float2(*(const __half2*)&v0.w);
        accA.x += w0 * p00.x;
        accA.y += w0 * p00.y;
        accA.z += w0 * p01.x;
        accA.w += w0 * p01.y;
        accB.x += w0 * p02.x;
        accB.y += w0 * p02.y;
        accB.z += w0 * p03.x;
        accB.w += w0 * p03.y;
        den += w0;
    }

    float d = den > EPS ? den : EPS;
    float inv = 1.0f / d;
    float4 b0 = ((const float4*)bias)[li * 2];
    float4 b1 = ((const float4*)bias)[li * 2 + 1];
    float4 o0, o1;
    o0.x = accA.x * inv + b0.x;
    o0.y = accA.y * inv + b0.y;
    o0.z = accA.z * inv + b0.z;
    o0.w = accA.w * inv + b0.w;
    o1.x = accB.x * inv + b1.x;
    o1.y = accB.y * inv + b1.y;
    o1.z = accB.z * inv + b1.z;
    o1.w = accB.w * inv + b1.w;
    float4* op = (float4*)(out + (size_t)node * HO) + li * 2;
    op[0] = o0;
    op[1] = o1;
}

extern "C" void kernel_launch(void* const* d_in, const int* in_sizes, int n_in,
                              void* d_out, int out_size) {
    const float* x = (const float*)d_in[0];
    const void* eidx = d_in[1];
    const float* W = (const float*)d_in[2];
    const float* att = (const float*)d_in[3];
    const float* bias = (const float*)d_in[4];
    float* out = (float*)d_out;

    static cudaStream_t s2 = nullptr;
    static cudaEvent_t ev_fork = nullptr, ev_join = nullptr;
    if (!s2) {
        cudaStreamCreateWithFlags(&s2, cudaStreamNonBlocking);
        cudaEventCreateWithFlags(&ev_fork, cudaEventDisableTiming);
        cudaEventCreateWithFlags(&ev_join, cudaEventDisableTiming);
        cudaFuncSetAttribute(gemm_kernel,
                             cudaFuncAttributeMaxDynamicSharedMemorySize, SMEM_TOTAL);
    }

    cudaEventRecord(ev_fork, 0);
    cudaStreamWaitEvent(s2, ev_fork, 0);

    // -- s2: GEMM path --
    wprep_kernel<<<(IN_CH * HO + 255) / 256, 256, 0, s2>>>(W);
    gemm_kernel<<<(N_NODES + 63) / 64, 128, SMEM_TOTAL, s2>>>(x, att);
    cudaEventRecord(ev_join, s2);

    // -- default stream: CSR build path --
    zero_detect_kernel<<<(N_NODES + 255) / 256, 256>>>((const unsigned int*)eidx);
    hist_kernel<<<(N_EDGES + 1023) / 1024, 256>>>(eidx);
    scan1_kernel<<<SCAN_NB, SCAN_B>>>();
    scan3_kernel<<<SCAN_NB, SCAN_B>>>();
    scatter_kernel<<<(N_EDGES + 255) / 256, 256>>>(eidx);

    cudaStreamWaitEvent(0, ev_join, 0);
    gather_kernel<<<((N_NODES + 1) / 2 * 32 + 255) / 256, 256>>>(out, bias);
}